// round 15
// baseline (speedup 1.0000x reference)
#include <cuda_runtime.h>
#include <cuda_fp16.h>

#define D 64
#define NODES_MAX 100000
#define MAXDEG 48
#define FIXSCALE 16777216.0f      // 2^24
#define FIXINV   5.9604645e-8f    // 2^-24

// ---- scratch (static __device__; no allocation anywhere) ----
__device__ float2 g_st[NODES_MAX];                 // {s, t}
__device__ unsigned long long g_pack[NODES_MAX];   // {cnt:hi32, diag_fix:lo32}
__device__ __half g_yh[(size_t)NODES_MAX * D];     // y, later scaled to dsi*y
__device__ float2 g_bkt[(size_t)NODES_MAX * MAXDEG]; // {col_as_int_bits, m1*m2}

// fast tanh: 1 - 2/(e^{2v}+1). MUFU.EX2 + MUFU.RCP, ~1e-7 abs error.
__device__ __forceinline__ float fast_tanh(float v) {
    const float e = __expf(2.0f * v);
    return 1.0f - __fdividef(2.0f, e + 1.0f);
}

// K1: per-node precompute. K-packed f32x2 FMA: thread j holds W_lin row j as
// 32 packed {w[2k],w[2k+1]} pairs; inner loop is LDS.64 + FFMA2 only.
// One node per 64-thread group, 4 nodes per 256-block iteration.
__global__ void __launch_bounds__(256) k_node_pre(
        const float* __restrict__ x,
        const float* __restrict__ Ws,
        const float* __restrict__ Wl,
        const float* __restrict__ bl,
        int N) {
    __shared__ float xs[4][D];
    const int g    = threadIdx.x >> 6;
    const int j    = threadIdx.x & 63;
    const int lane = threadIdx.x & 31;

    unsigned long long w2[32];   // {w[2k], w[2k+1]} pairs, preloaded once
    #pragma unroll
    for (int k = 0; k < 32; k++)
        w2[k] = *(const unsigned long long*)(Wl + j * D + 2 * k);
    const float bj = bl[j];
    const float wsA0 = Ws[lane],      wsA1 = Ws[lane + 32];
    const float wsB0 = Ws[64 + lane], wsB1 = Ws[96 + lane];

    for (int base = blockIdx.x * 4; base < N; base += gridDim.x * 4) {
        const int  node  = base + g;
        const bool valid = (node < N);
        __syncthreads();
        if (valid && j < 16)
            ((float4*)xs[g])[j] = ((const float4*)(x + (size_t)node * D))[j];
        __syncthreads();

        unsigned long long acc = 0ULL;   // {0.f, 0.f}
        #pragma unroll
        for (int k = 0; k < 32; k++) {
            const unsigned long long xv =
                *(const unsigned long long*)&xs[g][2 * k];
            asm("fma.rn.f32x2 %0, %1, %2, %3;"
                : "=l"(acc) : "l"(xv), "l"(w2[k]), "l"(acc));
        }
        float ye, yo;
        asm("mov.b64 {%0, %1}, %2;" : "=f"(ye), "=f"(yo) : "l"(acc));
        if (valid) g_yh[(size_t)node * D + j] = __float2half(ye + yo + bj);

        if (j < 32) {   // first warp of group: s,t reduction
            const float x0 = xs[g][lane], x1 = xs[g][lane + 32];
            float ps = x0 * wsA0 + x1 * wsA1;
            float pt = x0 * wsB0 + x1 * wsB1;
            #pragma unroll
            for (int off = 16; off; off >>= 1) {
                ps += __shfl_down_sync(0xffffffffu, ps, off);
                pt += __shfl_down_sync(0xffffffffu, pt, off);
            }
            if (lane == 0 && valid) {
                g_st[node]   = make_float2(ps, pt);
                g_pack[node] = 0ULL;
            }
        }
    }
}

// K2: two pairs per thread (R13 form). Packed u64 atomic per endpoint
// {cnt++, diag+=m^2} returns bucket slot; {col,w} written directly.
__global__ void k_edge_maps(const int* __restrict__ src,
                            const int* __restrict__ dst,
                            int Eh) {
    const int t = blockIdx.x * blockDim.x + threadIdx.x;
    const int e = 2 * t;
    if (e >= Eh) return;
    const int2 aa = *(const int2*)(src + e);
    const int2 bb = *(const int2*)(dst + e);

    const float2 st_a0 = __ldg(&g_st[aa.x]);
    const float2 st_b0 = __ldg(&g_st[bb.x]);
    const float2 st_a1 = __ldg(&g_st[aa.y]);
    const float2 st_b1 = __ldg(&g_st[bb.y]);

    const float m10 = fast_tanh(st_a0.x + st_b0.y);
    const float m20 = fast_tanh(st_b0.x + st_a0.y);
    const float m11 = fast_tanh(st_a1.x + st_b1.y);
    const float m21 = fast_tanh(st_b1.x + st_a1.y);
    const float w0 = m10 * m20;
    const float w1 = m11 * m21;

    const unsigned long long oa0 = atomicAdd(&g_pack[aa.x],
        (1ULL << 32) | __float2uint_rn(m10 * m10 * FIXSCALE));
    const unsigned long long ob0 = atomicAdd(&g_pack[bb.x],
        (1ULL << 32) | __float2uint_rn(m20 * m20 * FIXSCALE));
    const unsigned long long oa1 = atomicAdd(&g_pack[aa.y],
        (1ULL << 32) | __float2uint_rn(m11 * m11 * FIXSCALE));
    const unsigned long long ob1 = atomicAdd(&g_pack[bb.y],
        (1ULL << 32) | __float2uint_rn(m21 * m21 * FIXSCALE));

    float2 ent;
    ent.x = __int_as_float(bb.x); ent.y = w0;
    g_bkt[(size_t)aa.x * MAXDEG + (int)(oa0 >> 32)] = ent;
    ent.x = __int_as_float(aa.x);
    g_bkt[(size_t)bb.x * MAXDEG + (int)(ob0 >> 32)] = ent;
    ent.x = __int_as_float(bb.y); ent.y = w1;
    g_bkt[(size_t)aa.y * MAXDEG + (int)(oa1 >> 32)] = ent;
    ent.x = __int_as_float(aa.y);
    g_bkt[(size_t)bb.y * MAXDEG + (int)(ob1 >> 32)] = ent;
}

// K3: scale yh rows by dsi (warp-cooperative, coalesced). dsi from pack.
__global__ void k_scale(int N) {
    const int lane = threadIdx.x & 31;
    const int wid  = threadIdx.x >> 5;
    const int node_base = (blockIdx.x * 8 + wid) * 32;
    const int i = node_base + lane;

    float dsi = 1.f;
    if (i < N) {
        const unsigned long long pk = g_pack[i];
        const float dg = (float)(unsigned)(pk & 0xffffffffu) * FIXINV;
        dsi = rsqrtf(dg + 1.f);
    }
    #pragma unroll 4
    for (int r = 0; r < 32; r++) {
        const int node = node_base + r;
        if (node >= N) break;
        const float dr = __shfl_sync(0xffffffffu, dsi, r);
        __half2* p = ((__half2*)g_yh) + (size_t)node * 32 + lane;
        const float2 val = __half22float2(*p);
        *p = __floats2half2_rn(val.x * dr, val.y * dr);
    }
}

__device__ __forceinline__ void acc4(float& a0, float& a1, float& a2, float& a3,
                                     const uint2 r, const float wv) {
    const float2 fa = __half22float2(*(const __half2*)&r.x);
    const float2 fb = __half22float2(*(const __half2*)&r.y);
    a0 = fmaf(wv, fa.x, a0); a1 = fmaf(wv, fa.y, a1);
    a2 = fmaf(wv, fb.x, a2); a3 = fmaf(wv, fb.y, a3);
}

// K4: fused gather, software-pipelined meta + hoisted epilogue loads.
__global__ void __launch_bounds__(256) k_gather(const float* __restrict__ x,
                                                float* __restrict__ out, int N) {
    const int node = (blockIdx.x * blockDim.x + threadIdx.x) >> 4;
    if (node >= N) return;
    const int l16 = threadIdx.x & 15;

    const unsigned long long pk = __ldg(&g_pack[node]);

    // hoisted epilogue loads: in flight during the whole edge loop
    const uint2  ro = __ldg((const uint2*)(g_yh + (size_t)node * D) + l16);
    const float4 xv = __ldg((const float4*)(x + (size_t)node * D) + l16);

    const int   deg = (int)(pk >> 32);
    const float dg  = (float)(unsigned)(pk & 0xffffffffu) * FIXINV;
    const float dsi = rsqrtf(dg + 1.f);

    const float2* __restrict__ row = g_bkt + (size_t)node * MAXDEG;

    float a0 = 0.f, a1 = 0.f, a2 = 0.f, a3 = 0.f;
    int k = 0;
    float4 mA, mB;
    if (deg >= 4) {
        mA = __ldg((const float4*)row);
        mB = __ldg((const float4*)(row + 2));
    }
    for (; k + 8 <= deg; k += 4) {
        const float4 nA = __ldg((const float4*)(row + k + 4));
        const float4 nB = __ldg((const float4*)(row + k + 6));
        const uint2 r0 = __ldg((const uint2*)(g_yh + (size_t)__float_as_int(mA.x) * D) + l16);
        const uint2 r1 = __ldg((const uint2*)(g_yh + (size_t)__float_as_int(mA.z) * D) + l16);
        const uint2 r2 = __ldg((const uint2*)(g_yh + (size_t)__float_as_int(mB.x) * D) + l16);
        const uint2 r3 = __ldg((const uint2*)(g_yh + (size_t)__float_as_int(mB.z) * D) + l16);
        acc4(a0, a1, a2, a3, r0, mA.y);
        acc4(a0, a1, a2, a3, r1, mA.w);
        acc4(a0, a1, a2, a3, r2, mB.y);
        acc4(a0, a1, a2, a3, r3, mB.w);
        mA = nA; mB = nB;
    }
    if (k + 4 <= deg) {
        const uint2 r0 = __ldg((const uint2*)(g_yh + (size_t)__float_as_int(mA.x) * D) + l16);
        const uint2 r1 = __ldg((const uint2*)(g_yh + (size_t)__float_as_int(mA.z) * D) + l16);
        const uint2 r2 = __ldg((const uint2*)(g_yh + (size_t)__float_as_int(mB.x) * D) + l16);
        const uint2 r3 = __ldg((const uint2*)(g_yh + (size_t)__float_as_int(mB.z) * D) + l16);
        acc4(a0, a1, a2, a3, r0, mA.y);
        acc4(a0, a1, a2, a3, r1, mA.w);
        acc4(a0, a1, a2, a3, r2, mB.y);
        acc4(a0, a1, a2, a3, r3, mB.w);
        k += 4;
    }
    for (; k < deg; k++) {
        const float2 m0 = __ldg(&row[k]);
        const uint2 r0 = __ldg((const uint2*)(g_yh + (size_t)__float_as_int(m0.x) * D) + l16);
        acc4(a0, a1, a2, a3, r0, m0.y);
    }

    const float cown = dg * dsi;   // cd/dsi
    const float2 ya = __half22float2(*(const __half2*)&ro.x);
    const float2 yb = __half22float2(*(const __half2*)&ro.y);
    float4 o;
    o.x = xv.x - cown * ya.x + dsi * a0;
    o.y = xv.y - cown * ya.y + dsi * a1;
    o.z = xv.z - cown * yb.x + dsi * a2;
    o.w = xv.w - cown * yb.y + dsi * a3;
    *((float4*)(out + (size_t)node * D) + l16) = o;
}

extern "C" void kernel_launch(void* const* d_in, const int* in_sizes, int n_in,
                              void* d_out, int out_size) {
    const float* x  = (const float*)d_in[0];
    const float* Ws = (const float*)d_in[1];
    const float* Wl = (const float*)d_in[2];
    const float* bl = (const float*)d_in[3];
    const int*   ei = (const int*)d_in[4];

    const int N  = in_sizes[0] / D;
    const int E  = in_sizes[4] / 2;
    const int Eh = E / 2;
    const int* src = ei;           // row[e] for e < Eh
    const int* dst = ei + E;       // col[e] for e < Eh

    k_node_pre<<<1184, 256>>>(x, Ws, Wl, bl, N);
    k_edge_maps<<<(Eh / 2 + 255) / 256, 256>>>(src, dst, Eh);
    k_scale<<<(N + 255) / 256, 256>>>(N);
    k_gather<<<(N * 16 + 255) / 256, 256>>>(x, (float*)d_out, N);
}

// round 16
// speedup vs baseline: 1.2100x; 1.2100x over previous
#include <cuda_runtime.h>
#include <cuda_fp16.h>

#define D 64
#define NODES_MAX 100000
#define MAXDEG 48
#define FIXSCALE 16777216.0f      // 2^24
#define FIXINV   5.9604645e-8f    // 2^-24

// ---- scratch (static __device__; no allocation anywhere) ----
__device__ float2 g_st[NODES_MAX];                 // {s, t}
__device__ unsigned long long g_pack[NODES_MAX];   // {cnt:hi32, diag_fix:lo32}
__device__ __half g_yh[(size_t)NODES_MAX * D];     // y, later scaled to dsi*y
__device__ float2 g_bkt[(size_t)NODES_MAX * MAXDEG]; // {col_as_int_bits, m1*m2}

// fast tanh: 1 - 2/(e^{2v}+1). MUFU.EX2 + MUFU.RCP, ~1e-7 abs error.
__device__ __forceinline__ float fast_tanh(float v) {
    const float e = __expf(2.0f * v);
    return 1.0f - __fdividef(2.0f, e + 1.0f);
}

// K0: s,t per node + zero pack. One warp per node, lane owns 2 elems.
__global__ void __launch_bounds__(256) k_st(const float* __restrict__ x,
                                            const float* __restrict__ Ws,
                                            int N) {
    const int node = (blockIdx.x * blockDim.x + threadIdx.x) >> 5;
    if (node >= N) return;
    const int lane = threadIdx.x & 31;
    const float2 xv = __ldg((const float2*)(x + (size_t)node * D) + lane);
    const float wa0 = __ldg(Ws + 2 * lane),      wa1 = __ldg(Ws + 2 * lane + 1);
    const float wb0 = __ldg(Ws + 64 + 2 * lane), wb1 = __ldg(Ws + 64 + 2 * lane + 1);
    float ps = xv.x * wa0 + xv.y * wa1;
    float pt = xv.x * wb0 + xv.y * wb1;
    #pragma unroll
    for (int off = 16; off; off >>= 1) {
        ps += __shfl_down_sync(0xffffffffu, ps, off);
        pt += __shfl_down_sync(0xffffffffu, pt, off);
    }
    if (lane == 0) {
        g_st[node]   = make_float2(ps, pt);
        g_pack[node] = 0ULL;
    }
}

// K1: yh GEMM only (R13 form): packed f32x2 FMA, 2 nodes per 64-thread group.
__global__ void k_yh(const float* __restrict__ x,
                     const float* __restrict__ Wl,
                     const float* __restrict__ bl,
                     int N) {
    __shared__ float2 xs2[4][D];   // [group][k] = {xA[k], xB[k]}
    const int g = threadIdx.x >> 6;
    const int j = threadIdx.x & 63;

    float w[D];
    #pragma unroll
    for (int k = 0; k < D; k += 4) {
        float4 v = *(const float4*)(Wl + j * D + k);
        w[k] = v.x; w[k + 1] = v.y; w[k + 2] = v.z; w[k + 3] = v.w;
    }
    const float bj = bl[j];

    for (int base = blockIdx.x * 8; base < N; base += gridDim.x * 8) {
        const int nA = base + 2 * g;
        const int nB = nA + 1;
        const bool vA = (nA < N), vB = (nB < N);
        __syncthreads();
        if (j < 16) {
            if (vA) {
                const float4 v = ((const float4*)(x + (size_t)nA * D))[j];
                xs2[g][4*j+0].x = v.x; xs2[g][4*j+1].x = v.y;
                xs2[g][4*j+2].x = v.z; xs2[g][4*j+3].x = v.w;
            }
        } else if (j < 32) {
            const int jj = j - 16;
            if (vB) {
                const float4 v = ((const float4*)(x + (size_t)nB * D))[jj];
                xs2[g][4*jj+0].y = v.x; xs2[g][4*jj+1].y = v.y;
                xs2[g][4*jj+2].y = v.z; xs2[g][4*jj+3].y = v.w;
            }
        }
        __syncthreads();

        unsigned long long acc;
        asm("mov.b64 %0, {%1, %1};" : "=l"(acc) : "f"(bj));
        #pragma unroll
        for (int k = 0; k < D; k++) {
            const unsigned long long xv =
                *(const unsigned long long*)&xs2[g][k];
            unsigned long long wp;
            asm("mov.b64 %0, {%1, %1};" : "=l"(wp) : "f"(w[k]));
            asm("fma.rn.f32x2 %0, %1, %2, %3;"
                : "=l"(acc) : "l"(xv), "l"(wp), "l"(acc));
        }
        float yA, yB;
        asm("mov.b64 {%0, %1}, %2;" : "=f"(yA), "=f"(yB) : "l"(acc));
        if (vA) g_yh[(size_t)nA * D + j] = __float2half(yA);
        if (vB) g_yh[(size_t)nB * D + j] = __float2half(yB);
    }
}

// K2: two pairs per thread (R13 form). Packed u64 atomic per endpoint
// {cnt++, diag+=m^2} returns bucket slot; {col,w} written directly.
__global__ void k_edge_maps(const int* __restrict__ src,
                            const int* __restrict__ dst,
                            int Eh) {
    const int t = blockIdx.x * blockDim.x + threadIdx.x;
    const int e = 2 * t;
    if (e >= Eh) return;
    const int2 aa = *(const int2*)(src + e);
    const int2 bb = *(const int2*)(dst + e);

    const float2 st_a0 = __ldg(&g_st[aa.x]);
    const float2 st_b0 = __ldg(&g_st[bb.x]);
    const float2 st_a1 = __ldg(&g_st[aa.y]);
    const float2 st_b1 = __ldg(&g_st[bb.y]);

    const float m10 = fast_tanh(st_a0.x + st_b0.y);
    const float m20 = fast_tanh(st_b0.x + st_a0.y);
    const float m11 = fast_tanh(st_a1.x + st_b1.y);
    const float m21 = fast_tanh(st_b1.x + st_a1.y);
    const float w0 = m10 * m20;
    const float w1 = m11 * m21;

    const unsigned long long oa0 = atomicAdd(&g_pack[aa.x],
        (1ULL << 32) | __float2uint_rn(m10 * m10 * FIXSCALE));
    const unsigned long long ob0 = atomicAdd(&g_pack[bb.x],
        (1ULL << 32) | __float2uint_rn(m20 * m20 * FIXSCALE));
    const unsigned long long oa1 = atomicAdd(&g_pack[aa.y],
        (1ULL << 32) | __float2uint_rn(m11 * m11 * FIXSCALE));
    const unsigned long long ob1 = atomicAdd(&g_pack[bb.y],
        (1ULL << 32) | __float2uint_rn(m21 * m21 * FIXSCALE));

    float2 ent;
    ent.x = __int_as_float(bb.x); ent.y = w0;
    g_bkt[(size_t)aa.x * MAXDEG + (int)(oa0 >> 32)] = ent;
    ent.x = __int_as_float(aa.x);
    g_bkt[(size_t)bb.x * MAXDEG + (int)(ob0 >> 32)] = ent;
    ent.x = __int_as_float(bb.y); ent.y = w1;
    g_bkt[(size_t)aa.y * MAXDEG + (int)(oa1 >> 32)] = ent;
    ent.x = __int_as_float(aa.y);
    g_bkt[(size_t)bb.y * MAXDEG + (int)(ob1 >> 32)] = ent;
}

// K3: scale yh rows by dsi (warp-cooperative, coalesced). dsi from pack.
__global__ void k_scale(int N) {
    const int lane = threadIdx.x & 31;
    const int wid  = threadIdx.x >> 5;
    const int node_base = (blockIdx.x * 8 + wid) * 32;
    const int i = node_base + lane;

    float dsi = 1.f;
    if (i < N) {
        const unsigned long long pk = g_pack[i];
        const float dg = (float)(unsigned)(pk & 0xffffffffu) * FIXINV;
        dsi = rsqrtf(dg + 1.f);
    }
    #pragma unroll 4
    for (int r = 0; r < 32; r++) {
        const int node = node_base + r;
        if (node >= N) break;
        const float dr = __shfl_sync(0xffffffffu, dsi, r);
        __half2* p = ((__half2*)g_yh) + (size_t)node * 32 + lane;
        const float2 val = __half22float2(*p);
        *p = __floats2half2_rn(val.x * dr, val.y * dr);
    }
}

__device__ __forceinline__ void acc4(float& a0, float& a1, float& a2, float& a3,
                                     const uint2 r, const float wv) {
    const float2 fa = __half22float2(*(const __half2*)&r.x);
    const float2 fb = __half22float2(*(const __half2*)&r.y);
    a0 = fmaf(wv, fa.x, a0); a1 = fmaf(wv, fa.y, a1);
    a2 = fmaf(wv, fb.x, a2); a3 = fmaf(wv, fb.y, a3);
}

// K4: fused gather, software-pipelined meta + hoisted epilogue loads.
__global__ void __launch_bounds__(256) k_gather(const float* __restrict__ x,
                                                float* __restrict__ out, int N) {
    const int node = (blockIdx.x * blockDim.x + threadIdx.x) >> 4;
    if (node >= N) return;
    const int l16 = threadIdx.x & 15;

    const unsigned long long pk = __ldg(&g_pack[node]);
    const uint2  ro = __ldg((const uint2*)(g_yh + (size_t)node * D) + l16);
    const float4 xv = __ldg((const float4*)(x + (size_t)node * D) + l16);

    const int   deg = (int)(pk >> 32);
    const float dg  = (float)(unsigned)(pk & 0xffffffffu) * FIXINV;
    const float dsi = rsqrtf(dg + 1.f);

    const float2* __restrict__ row = g_bkt + (size_t)node * MAXDEG;

    float a0 = 0.f, a1 = 0.f, a2 = 0.f, a3 = 0.f;
    int k = 0;
    float4 mA, mB;
    if (deg >= 4) {
        mA = __ldg((const float4*)row);
        mB = __ldg((const float4*)(row + 2));
    }
    for (; k + 8 <= deg; k += 4) {
        const float4 nA = __ldg((const float4*)(row + k + 4));
        const float4 nB = __ldg((const float4*)(row + k + 6));
        const uint2 r0 = __ldg((const uint2*)(g_yh + (size_t)__float_as_int(mA.x) * D) + l16);
        const uint2 r1 = __ldg((const uint2*)(g_yh + (size_t)__float_as_int(mA.z) * D) + l16);
        const uint2 r2 = __ldg((const uint2*)(g_yh + (size_t)__float_as_int(mB.x) * D) + l16);
        const uint2 r3 = __ldg((const uint2*)(g_yh + (size_t)__float_as_int(mB.z) * D) + l16);
        acc4(a0, a1, a2, a3, r0, mA.y);
        acc4(a0, a1, a2, a3, r1, mA.w);
        acc4(a0, a1, a2, a3, r2, mB.y);
        acc4(a0, a1, a2, a3, r3, mB.w);
        mA = nA; mB = nB;
    }
    if (k + 4 <= deg) {
        const uint2 r0 = __ldg((const uint2*)(g_yh + (size_t)__float_as_int(mA.x) * D) + l16);
        const uint2 r1 = __ldg((const uint2*)(g_yh + (size_t)__float_as_int(mA.z) * D) + l16);
        const uint2 r2 = __ldg((const uint2*)(g_yh + (size_t)__float_as_int(mB.x) * D) + l16);
        const uint2 r3 = __ldg((const uint2*)(g_yh + (size_t)__float_as_int(mB.z) * D) + l16);
        acc4(a0, a1, a2, a3, r0, mA.y);
        acc4(a0, a1, a2, a3, r1, mA.w);
        acc4(a0, a1, a2, a3, r2, mB.y);
        acc4(a0, a1, a2, a3, r3, mB.w);
        k += 4;
    }
    for (; k < deg; k++) {
        const float2 m0 = __ldg(&row[k]);
        const uint2 r0 = __ldg((const uint2*)(g_yh + (size_t)__float_as_int(m0.x) * D) + l16);
        acc4(a0, a1, a2, a3, r0, m0.y);
    }

    const float cown = dg * dsi;   // cd/dsi
    const float2 ya = __half22float2(*(const __half2*)&ro.x);
    const float2 yb = __half22float2(*(const __half2*)&ro.y);
    float4 o;
    o.x = xv.x - cown * ya.x + dsi * a0;
    o.y = xv.y - cown * ya.y + dsi * a1;
    o.z = xv.z - cown * yb.x + dsi * a2;
    o.w = xv.w - cown * yb.y + dsi * a3;
    *((float4*)(out + (size_t)node * D) + l16) = o;
}

extern "C" void kernel_launch(void* const* d_in, const int* in_sizes, int n_in,
                              void* d_out, int out_size) {
    const float* x  = (const float*)d_in[0];
    const float* Ws = (const float*)d_in[1];
    const float* Wl = (const float*)d_in[2];
    const float* bl = (const float*)d_in[3];
    const int*   ei = (const int*)d_in[4];

    const int N  = in_sizes[0] / D;
    const int E  = in_sizes[4] / 2;
    const int Eh = E / 2;
    const int* src = ei;           // row[e] for e < Eh
    const int* dst = ei + E;       // col[e] for e < Eh

    // fork/join: k_yh (side stream) overlaps k_edge_maps (capture stream).
    cudaStream_t s2;
    cudaEvent_t ev_fork, ev_join;
    cudaStreamCreateWithFlags(&s2, cudaStreamNonBlocking);
    cudaEventCreateWithFlags(&ev_fork, cudaEventDisableTiming);
    cudaEventCreateWithFlags(&ev_join, cudaEventDisableTiming);

    k_st<<<(N * 32 + 255) / 256, 256>>>(x, Ws, N);
    cudaEventRecord(ev_fork, 0);
    cudaStreamWaitEvent(s2, ev_fork, 0);

    k_yh<<<1184, 256, 0, s2>>>(x, Wl, bl, N);                 // side stream
    k_edge_maps<<<(Eh / 2 + 255) / 256, 256>>>(src, dst, Eh); // capture stream

    cudaEventRecord(ev_join, s2);
    cudaStreamWaitEvent(0, ev_join, 0);

    k_scale<<<(N + 255) / 256, 256>>>(N);
    k_gather<<<(N * 16 + 255) / 256, 256>>>(x, (float*)d_out, N);
}

// round 17
// speedup vs baseline: 1.2519x; 1.0346x over previous
#include <cuda_runtime.h>
#include <cuda_fp16.h>

#define D 64
#define NODES_MAX 100000
#define MAXDEG 48
#define FIXSCALE 16777216.0f      // 2^24
#define FIXINV   5.9604645e-8f    // 2^-24

// ---- scratch (static __device__; no allocation anywhere) ----
__device__ float2 g_st[NODES_MAX];                 // {s, t}
__device__ unsigned long long g_pack[NODES_MAX];   // {cnt:hi32, diag_fix:lo32}
__device__ __half g_yh[(size_t)NODES_MAX * D];     // y, later scaled to dsi*y
__device__ float2 g_bkt[(size_t)NODES_MAX * MAXDEG]; // {col_as_int_bits, m1*m2}

// fast tanh: 1 - 2/(e^{2v}+1). MUFU.EX2 + MUFU.RCP, ~1e-7 abs error.
__device__ __forceinline__ float fast_tanh(float v) {
    const float e = __expf(2.0f * v);
    return 1.0f - __fdividef(2.0f, e + 1.0f);
}

// K0: s,t per node + zero pack. One warp per node, lane owns 2 elems.
__global__ void __launch_bounds__(256) k_st(const float* __restrict__ x,
                                            const float* __restrict__ Ws,
                                            int N) {
    const int node = (blockIdx.x * blockDim.x + threadIdx.x) >> 5;
    if (node >= N) return;
    const int lane = threadIdx.x & 31;
    const float2 xv = __ldg((const float2*)(x + (size_t)node * D) + lane);
    const float wa0 = __ldg(Ws + 2 * lane),      wa1 = __ldg(Ws + 2 * lane + 1);
    const float wb0 = __ldg(Ws + 64 + 2 * lane), wb1 = __ldg(Ws + 64 + 2 * lane + 1);
    float ps = xv.x * wa0 + xv.y * wa1;
    float pt = xv.x * wb0 + xv.y * wb1;
    #pragma unroll
    for (int off = 16; off; off >>= 1) {
        ps += __shfl_down_sync(0xffffffffu, ps, off);
        pt += __shfl_down_sync(0xffffffffu, pt, off);
    }
    if (lane == 0) {
        g_st[node]   = make_float2(ps, pt);
        g_pack[node] = 0ULL;
    }
}

// K1: yh GEMM only: packed f32x2 FMA, 2 nodes per 64-thread group.
__global__ void k_yh(const float* __restrict__ x,
                     const float* __restrict__ Wl,
                     const float* __restrict__ bl,
                     int N) {
    __shared__ float2 xs2[4][D];   // [group][k] = {xA[k], xB[k]}
    const int g = threadIdx.x >> 6;
    const int j = threadIdx.x & 63;

    float w[D];
    #pragma unroll
    for (int k = 0; k < D; k += 4) {
        float4 v = *(const float4*)(Wl + j * D + k);
        w[k] = v.x; w[k + 1] = v.y; w[k + 2] = v.z; w[k + 3] = v.w;
    }
    const float bj = bl[j];

    for (int base = blockIdx.x * 8; base < N; base += gridDim.x * 8) {
        const int nA = base + 2 * g;
        const int nB = nA + 1;
        const bool vA = (nA < N), vB = (nB < N);
        __syncthreads();
        if (j < 16) {
            if (vA) {
                const float4 v = ((const float4*)(x + (size_t)nA * D))[j];
                xs2[g][4*j+0].x = v.x; xs2[g][4*j+1].x = v.y;
                xs2[g][4*j+2].x = v.z; xs2[g][4*j+3].x = v.w;
            }
        } else if (j < 32) {
            const int jj = j - 16;
            if (vB) {
                const float4 v = ((const float4*)(x + (size_t)nB * D))[jj];
                xs2[g][4*jj+0].y = v.x; xs2[g][4*jj+1].y = v.y;
                xs2[g][4*jj+2].y = v.z; xs2[g][4*jj+3].y = v.w;
            }
        }
        __syncthreads();

        unsigned long long acc;
        asm("mov.b64 %0, {%1, %1};" : "=l"(acc) : "f"(bj));
        #pragma unroll
        for (int k = 0; k < D; k++) {
            const unsigned long long xv =
                *(const unsigned long long*)&xs2[g][k];
            unsigned long long wp;
            asm("mov.b64 %0, {%1, %1};" : "=l"(wp) : "f"(w[k]));
            asm("fma.rn.f32x2 %0, %1, %2, %3;"
                : "=l"(acc) : "l"(xv), "l"(wp), "l"(acc));
        }
        float yA, yB;
        asm("mov.b64 {%0, %1}, %2;" : "=f"(yA), "=f"(yB) : "l"(acc));
        if (vA) g_yh[(size_t)nA * D + j] = __float2half(yA);
        if (vB) g_yh[(size_t)nB * D + j] = __float2half(yB);
    }
}

// K2: two pairs per thread. Packed u64 atomic per endpoint {cnt++, diag+=m^2}
// returns bucket slot; {col,w} written directly into fixed-stride buckets.
__global__ void k_edge_maps(const int* __restrict__ src,
                            const int* __restrict__ dst,
                            int Eh) {
    const int t = blockIdx.x * blockDim.x + threadIdx.x;
    const int e = 2 * t;
    if (e >= Eh) return;
    const int2 aa = *(const int2*)(src + e);
    const int2 bb = *(const int2*)(dst + e);

    const float2 st_a0 = __ldg(&g_st[aa.x]);
    const float2 st_b0 = __ldg(&g_st[bb.x]);
    const float2 st_a1 = __ldg(&g_st[aa.y]);
    const float2 st_b1 = __ldg(&g_st[bb.y]);

    const float m10 = fast_tanh(st_a0.x + st_b0.y);
    const float m20 = fast_tanh(st_b0.x + st_a0.y);
    const float m11 = fast_tanh(st_a1.x + st_b1.y);
    const float m21 = fast_tanh(st_b1.x + st_a1.y);
    const float w0 = m10 * m20;
    const float w1 = m11 * m21;

    const unsigned long long oa0 = atomicAdd(&g_pack[aa.x],
        (1ULL << 32) | __float2uint_rn(m10 * m10 * FIXSCALE));
    const unsigned long long ob0 = atomicAdd(&g_pack[bb.x],
        (1ULL << 32) | __float2uint_rn(m20 * m20 * FIXSCALE));
    const unsigned long long oa1 = atomicAdd(&g_pack[aa.y],
        (1ULL << 32) | __float2uint_rn(m11 * m11 * FIXSCALE));
    const unsigned long long ob1 = atomicAdd(&g_pack[bb.y],
        (1ULL << 32) | __float2uint_rn(m21 * m21 * FIXSCALE));

    float2 ent;
    ent.x = __int_as_float(bb.x); ent.y = w0;
    g_bkt[(size_t)aa.x * MAXDEG + (int)(oa0 >> 32)] = ent;
    ent.x = __int_as_float(aa.x);
    g_bkt[(size_t)bb.x * MAXDEG + (int)(ob0 >> 32)] = ent;
    ent.x = __int_as_float(bb.y); ent.y = w1;
    g_bkt[(size_t)aa.y * MAXDEG + (int)(oa1 >> 32)] = ent;
    ent.x = __int_as_float(aa.y);
    g_bkt[(size_t)bb.y * MAXDEG + (int)(ob1 >> 32)] = ent;
}

// K3: flat scale: one warp per node, one thread per half2 element.
// No loops, no serial chain — pure bandwidth.
__global__ void __launch_bounds__(256) k_scale(int N) {
    const int tid  = blockIdx.x * blockDim.x + threadIdx.x;
    const int node = tid >> 5;
    if (node >= N) return;
    const int lane = tid & 31;

    const unsigned long long pk = __ldg(&g_pack[node]);   // broadcast in warp
    const float dg  = (float)(unsigned)(pk & 0xffffffffu) * FIXINV;
    const float dsi = rsqrtf(dg + 1.f);

    __half2* p = ((__half2*)g_yh) + (size_t)node * 32 + lane;
    const float2 val = __half22float2(*p);
    *p = __floats2half2_rn(val.x * dsi, val.y * dsi);
}

__device__ __forceinline__ void acc4(float& a0, float& a1, float& a2, float& a3,
                                     const uint2 r, const float wv) {
    const float2 fa = __half22float2(*(const __half2*)&r.x);
    const float2 fb = __half22float2(*(const __half2*)&r.y);
    a0 = fmaf(wv, fa.x, a0); a1 = fmaf(wv, fa.y, a1);
    a2 = fmaf(wv, fb.x, a2); a3 = fmaf(wv, fb.y, a3);
}

// K4: fused gather, software-pipelined meta + hoisted epilogue loads.
__global__ void __launch_bounds__(256) k_gather(const float* __restrict__ x,
                                                float* __restrict__ out, int N) {
    const int node = (blockIdx.x * blockDim.x + threadIdx.x) >> 4;
    if (node >= N) return;
    const int l16 = threadIdx.x & 15;

    const unsigned long long pk = __ldg(&g_pack[node]);
    const uint2  ro = __ldg((const uint2*)(g_yh + (size_t)node * D) + l16);
    const float4 xv = __ldg((const float4*)(x + (size_t)node * D) + l16);

    const int   deg = (int)(pk >> 32);
    const float dg  = (float)(unsigned)(pk & 0xffffffffu) * FIXINV;
    const float dsi = rsqrtf(dg + 1.f);

    const float2* __restrict__ row = g_bkt + (size_t)node * MAXDEG;

    float a0 = 0.f, a1 = 0.f, a2 = 0.f, a3 = 0.f;
    int k = 0;
    float4 mA, mB;
    if (deg >= 4) {
        mA = __ldg((const float4*)row);
        mB = __ldg((const float4*)(row + 2));
    }
    for (; k + 8 <= deg; k += 4) {
        const float4 nA = __ldg((const float4*)(row + k + 4));
        const float4 nB = __ldg((const float4*)(row + k + 6));
        const uint2 r0 = __ldg((const uint2*)(g_yh + (size_t)__float_as_int(mA.x) * D) + l16);
        const uint2 r1 = __ldg((const uint2*)(g_yh + (size_t)__float_as_int(mA.z) * D) + l16);
        const uint2 r2 = __ldg((const uint2*)(g_yh + (size_t)__float_as_int(mB.x) * D) + l16);
        const uint2 r3 = __ldg((const uint2*)(g_yh + (size_t)__float_as_int(mB.z) * D) + l16);
        acc4(a0, a1, a2, a3, r0, mA.y);
        acc4(a0, a1, a2, a3, r1, mA.w);
        acc4(a0, a1, a2, a3, r2, mB.y);
        acc4(a0, a1, a2, a3, r3, mB.w);
        mA = nA; mB = nB;
    }
    if (k + 4 <= deg) {
        const uint2 r0 = __ldg((const uint2*)(g_yh + (size_t)__float_as_int(mA.x) * D) + l16);
        const uint2 r1 = __ldg((const uint2*)(g_yh + (size_t)__float_as_int(mA.z) * D) + l16);
        const uint2 r2 = __ldg((const uint2*)(g_yh + (size_t)__float_as_int(mB.x) * D) + l16);
        const uint2 r3 = __ldg((const uint2*)(g_yh + (size_t)__float_as_int(mB.z) * D) + l16);
        acc4(a0, a1, a2, a3, r0, mA.y);
        acc4(a0, a1, a2, a3, r1, mA.w);
        acc4(a0, a1, a2, a3, r2, mB.y);
        acc4(a0, a1, a2, a3, r3, mB.w);
        k += 4;
    }
    for (; k < deg; k++) {
        const float2 m0 = __ldg(&row[k]);
        const uint2 r0 = __ldg((const uint2*)(g_yh + (size_t)__float_as_int(m0.x) * D) + l16);
        acc4(a0, a1, a2, a3, r0, m0.y);
    }

    const float cown = dg * dsi;   // cd/dsi
    const float2 ya = __half22float2(*(const __half2*)&ro.x);
    const float2 yb = __half22float2(*(const __half2*)&ro.y);
    float4 o;
    o.x = xv.x - cown * ya.x + dsi * a0;
    o.y = xv.y - cown * ya.y + dsi * a1;
    o.z = xv.z - cown * yb.x + dsi * a2;
    o.w = xv.w - cown * yb.y + dsi * a3;
    *((float4*)(out + (size_t)node * D) + l16) = o;
}

extern "C" void kernel_launch(void* const* d_in, const int* in_sizes, int n_in,
                              void* d_out, int out_size) {
    const float* x  = (const float*)d_in[0];
    const float* Ws = (const float*)d_in[1];
    const float* Wl = (const float*)d_in[2];
    const float* bl = (const float*)d_in[3];
    const int*   ei = (const int*)d_in[4];

    const int N  = in_sizes[0] / D;
    const int E  = in_sizes[4] / 2;
    const int Eh = E / 2;
    const int* src = ei;           // row[e] for e < Eh
    const int* dst = ei + E;       // col[e] for e < Eh

    // fork/join: k_yh (side stream) overlaps k_edge_maps (capture stream).
    cudaStream_t s2;
    cudaEvent_t ev_fork, ev_join;
    cudaStreamCreateWithFlags(&s2, cudaStreamNonBlocking);
    cudaEventCreateWithFlags(&ev_fork, cudaEventDisableTiming);
    cudaEventCreateWithFlags(&ev_join, cudaEventDisableTiming);

    k_st<<<(N * 32 + 255) / 256, 256>>>(x, Ws, N);
    cudaEventRecord(ev_fork, 0);
    cudaStreamWaitEvent(s2, ev_fork, 0);

    k_yh<<<1184, 256, 0, s2>>>(x, Wl, bl, N);                 // side stream
    k_edge_maps<<<(Eh / 2 + 255) / 256, 256>>>(src, dst, Eh); // capture stream

    cudaEventRecord(ev_join, s2);
    cudaStreamWaitEvent(0, ev_join, 0);

    k_scale<<<(N * 32 + 255) / 256, 256>>>(N);
    k_gather<<<(N * 16 + 255) / 256, 256>>>(x, (float*)d_out, N);
}